// round 6
// baseline (speedup 1.0000x reference)
#include <cuda_runtime.h>
#include <math.h>

#define B 16
#define S 8192
#define C 256      // K_CH = D_MODEL
#define OUT 256
#define SB 64            // rows per scores block
#define NSB (S / SB)     // 128 score partials per batch
#define VB 128           // rows per value block
#define NVB (S / VB)     // 64 value partials per batch

// ---------------- scratch (no allocations allowed) ----------------
__device__ float g_qk[B * C];          // Wk @ q  per batch/channel
__device__ float g_bdot[B];            // q . bk
__device__ float g_scores[B * S];      // raw scaled scores
__device__ float g_pm[B * NSB];        // per-block max
__device__ float g_pl[B * NSB];        // per-block sumexp
__device__ float g_cv[B * NVB * C];    // per-block normalized weighted value sums
__device__ float g_ctx[B * OUT];       // final context row per batch

// ---------------- kernel 1: prep (grid (B,8), 256 thr) ---------------
// every block redundantly computes q (Wq stays L2-hot), then its 32
// channels of qk = Wk @ q; block y==0 also does bdot = q.bk
__global__ void prep_kernel(const float* __restrict__ query,
                            const float* __restrict__ Wq,
                            const float* __restrict__ bq,
                            const float* __restrict__ Wk,
                            const float* __restrict__ bk) {
    const int b = blockIdx.x;
    const int t = threadIdx.x;            // 0..255
    const int lane = t & 31, warp = t >> 5;
    __shared__ float q_sh[OUT];
    __shared__ float red[8];

    // redundant q projection (coalesced over t)
    float acc = bq[t];
    const float* qrow = query + b * C;
    #pragma unroll 8
    for (int d = 0; d < C; d++)
        acc += qrow[d] * Wq[d * OUT + t];
    q_sh[t] = acc;

    if (blockIdx.y == 0) {
        float v = acc * bk[t];
        #pragma unroll
        for (int off = 16; off; off >>= 1)
            v += __shfl_xor_sync(0xffffffffu, v, off);
        if (lane == 0) red[warp] = v;
    }
    __syncthreads();
    if (blockIdx.y == 0 && t == 0) {
        float s = red[0];
        #pragma unroll
        for (int i = 1; i < 8; i++) s += red[i];
        g_bdot[b] = s;
    }

    // qk: this block's 32 channels; warp handles 4 channels sequentially
    const float4* q4 = (const float4*)q_sh;
    #pragma unroll
    for (int i = 0; i < 4; i++) {
        const int c = blockIdx.y * 32 + warp * 4 + i;
        const float4* w4 = (const float4*)(Wk + (size_t)c * OUT);
        float a = 0.f;
        #pragma unroll
        for (int j = 0; j < 2; j++) {
            float4 w = w4[lane + 32 * j];
            float4 q = q4[lane + 32 * j];
            a += w.x * q.x + w.y * q.y + w.z * q.z + w.w * q.w;
        }
        #pragma unroll
        for (int off = 16; off; off >>= 1)
            a += __shfl_xor_sync(0xffffffffu, a, off);
        if (lane == 0) g_qk[b * C + c] = a;
    }
}

// ---------------- kernel 2: scores pass (grid (NSB,B), 256 thr) ------
// reads key once; each warp computes 8 rows, 4 in flight
__global__ void scores_kernel(const float* __restrict__ key) {
    const int b = blockIdx.y;
    const int s0 = blockIdx.x * SB;
    const int t = threadIdx.x, lane = t & 31, warp = t >> 5;

    __shared__ float qk_sh[C];
    __shared__ float sc_sh[SB];
    __shared__ float redm[2], redl[2];

    qk_sh[t] = g_qk[b * C + t];
    __syncthreads();

    const float bd = g_bdot[b];
    const float scale = 0.0625f;  // 1/sqrt(256)
    const float4* qk4 = (const float4*)qk_sh;

    #pragma unroll
    for (int half = 0; half < 2; half++) {
        const int r0 = warp * 8 + half * 4;
        const float* base = key + ((size_t)b * S + s0 + r0) * C;
        const float4* k0 = (const float4*)(base);
        const float4* k1 = (const float4*)(base + C);
        const float4* k2 = (const float4*)(base + 2 * C);
        const float4* k3 = (const float4*)(base + 3 * C);
        float a0 = 0.f, a1 = 0.f, a2 = 0.f, a3 = 0.f;
        #pragma unroll
        for (int j = 0; j < 2; j++) {
            const int idx = lane + 32 * j;
            float4 q = qk4[idx];
            float4 x0 = k0[idx];
            float4 x1 = k1[idx];
            float4 x2 = k2[idx];
            float4 x3 = k3[idx];
            a0 += x0.x * q.x + x0.y * q.y + x0.z * q.z + x0.w * q.w;
            a1 += x1.x * q.x + x1.y * q.y + x1.z * q.z + x1.w * q.w;
            a2 += x2.x * q.x + x2.y * q.y + x2.z * q.z + x2.w * q.w;
            a3 += x3.x * q.x + x3.y * q.y + x3.z * q.z + x3.w * q.w;
        }
        #pragma unroll
        for (int off = 16; off; off >>= 1) {
            a0 += __shfl_xor_sync(0xffffffffu, a0, off);
            a1 += __shfl_xor_sync(0xffffffffu, a1, off);
            a2 += __shfl_xor_sync(0xffffffffu, a2, off);
            a3 += __shfl_xor_sync(0xffffffffu, a3, off);
        }
        if (lane == 0) {
            sc_sh[r0]     = (a0 + bd) * scale;
            sc_sh[r0 + 1] = (a1 + bd) * scale;
            sc_sh[r0 + 2] = (a2 + bd) * scale;
            sc_sh[r0 + 3] = (a3 + bd) * scale;
        }
    }
    __syncthreads();

    // write raw scores + block-local softmax partials (threads 0..63)
    float sc = 0.f;
    if (t < SB) {
        sc = sc_sh[t];
        g_scores[(size_t)b * S + s0 + t] = sc;
        float v = sc;
        #pragma unroll
        for (int off = 16; off; off >>= 1)
            v = fmaxf(v, __shfl_xor_sync(0xffffffffu, v, off));
        if (lane == 0) redm[warp] = v;
    }
    __syncthreads();
    const float bm = fmaxf(redm[0], redm[1]);
    if (t < SB) {
        float p = __expf(sc - bm);
        #pragma unroll
        for (int off = 16; off; off >>= 1)
            p += __shfl_xor_sync(0xffffffffu, p, off);
        if (lane == 0) redl[warp] = p;
    }
    __syncthreads();
    if (t == 0) {
        g_pm[b * NSB + blockIdx.x] = bm;
        g_pl[b * NSB + blockIdx.x] = redl[0] + redl[1];
    }
}

// ---------------- kernel 3: value pass w/ fused global softmax -------
// grid (NVB, B), 256 thr; redundant L2-hot reduce of 128 partials,
// then float4 column walk: 4 row-groups x 64 channel-quads
__global__ void vaccum_kernel(const float* __restrict__ value) {
    const int b = blockIdx.y;
    const int s0 = blockIdx.x * VB;
    const int t = threadIdx.x, lane = t & 31, warp = t >> 5;

    __shared__ float w_sh[VB];
    __shared__ float redm[4], redl[4];
    __shared__ float4 red4[4][OUT / 4];

    // --- redundant global softmax reduce over NSB=128 partials (L2 hot)
    float pm = -INFINITY, pl = 0.f;
    if (t < NSB) {
        pm = g_pm[b * NSB + t];
        pl = g_pl[b * NSB + t];
    }
    float v = pm;
    #pragma unroll
    for (int off = 16; off; off >>= 1)
        v = fmaxf(v, __shfl_xor_sync(0xffffffffu, v, off));
    if (lane == 0) redm[warp] = v;
    __syncthreads();
    const float gm = fmaxf(fmaxf(redm[0], redm[1]), fmaxf(redm[2], redm[3]));
    float w = pl * __expf(pm - gm);
    #pragma unroll
    for (int off = 16; off; off >>= 1)
        w += __shfl_xor_sync(0xffffffffu, w, off);
    if (lane == 0) redl[warp] = w;
    __syncthreads();
    const float gli = 1.f / (redl[0] + redl[1] + redl[2] + redl[3]);

    // --- per-row weights for this chunk
    if (t < VB)
        w_sh[t] = __expf(g_scores[(size_t)b * S + s0 + t] - gm) * gli;
    __syncthreads();

    // --- float4 column walk: rg = row-group, cq = channel quad
    const int cq = t & 63;
    const int rg = t >> 6;
    const float4* vb = (const float4*)(value + ((size_t)b * S + s0) * C) + cq;
    float4 acc = make_float4(0.f, 0.f, 0.f, 0.f);
    #pragma unroll 4
    for (int s = rg; s < VB; s += 4) {
        const float4 x = vb[(size_t)s * (C / 4)];
        const float ws = w_sh[s];
        acc.x += ws * x.x; acc.y += ws * x.y;
        acc.z += ws * x.z; acc.w += ws * x.w;
    }
    red4[rg][cq] = acc;
    __syncthreads();

    if (t < 64) {
        float4 a0 = red4[0][t], a1 = red4[1][t], a2 = red4[2][t], a3 = red4[3][t];
        float4 r;
        r.x = (a0.x + a1.x) + (a2.x + a3.x);
        r.y = (a0.y + a1.y) + (a2.y + a3.y);
        r.z = (a0.z + a1.z) + (a2.z + a3.z);
        r.w = (a0.w + a1.w) + (a2.w + a3.w);
        ((float4*)(g_cv + ((size_t)(b * NVB + blockIdx.x)) * C))[t] = r;
    }
}

// ---------------- kernel 4: sum partials + Wv projection (grid B) ----
__global__ void project_kernel(const float* __restrict__ Wv,
                               const float* __restrict__ bv) {
    const int b = blockIdx.x, t = threadIdx.x;
    float acc = 0.f;
    #pragma unroll 8
    for (int i = 0; i < NVB; i++)
        acc += g_cv[((size_t)(b * NVB + i)) * C + t];   // coalesced over t

    __shared__ float cx_sh[C];
    cx_sh[t] = acc;
    __syncthreads();

    float o = bv[t];
    #pragma unroll 8
    for (int c = 0; c < C; c++)
        o += cx_sh[c] * Wv[c * OUT + t];                // coalesced over t
    g_ctx[b * OUT + t] = o;
}

// ---------------- kernel 5: broadcast ctx row over S -----------------
__global__ void bcast_kernel(float* __restrict__ out) {
    const int b = blockIdx.y;
    const int t = threadIdx.x;
    __shared__ float4 ctx4[OUT / 4];  // 64
    if (t < OUT / 4)
        ctx4[t] = ((const float4*)(g_ctx + b * OUT))[t];
    __syncthreads();

    const int row = t >> 6;   // 0..3
    const int col = t & 63;   // 0..63
    const float4 val = ctx4[col];
    float4* o4 = (float4*)out;
    const size_t base = ((size_t)b * S + (size_t)blockIdx.x * 64) * (C / 4);
    #pragma unroll
    for (int i = 0; i < 16; i++)
        __stcs(&o4[base + (size_t)(i * 4 + row) * (OUT / 4) + col], val);
}

// ---------------- launch ------------------
extern "C" void kernel_launch(void* const* d_in, const int* in_sizes, int n_in,
                              void* d_out, int out_size) {
    const float* query = (const float*)d_in[0];
    const float* key   = (const float*)d_in[1];
    const float* value = (const float*)d_in[2];
    const float* Wq    = (const float*)d_in[3];
    const float* bq    = (const float*)d_in[4];
    const float* Wk    = (const float*)d_in[5];
    const float* bk    = (const float*)d_in[6];
    const float* Wv    = (const float*)d_in[7];
    const float* bv    = (const float*)d_in[8];
    float* out = (float*)d_out;

    prep_kernel<<<dim3(B, 8), 256>>>(query, Wq, bq, Wk, bk);
    scores_kernel<<<dim3(NSB, B), 256>>>(key);
    vaccum_kernel<<<dim3(NVB, B), 256>>>(value);
    project_kernel<<<B, 256>>>(Wv, bv);
    bcast_kernel<<<dim3(S / 64, B), 256>>>(out);
}

// round 7
// speedup vs baseline: 1.1271x; 1.1271x over previous
#include <cuda_runtime.h>
#include <math.h>

#define B 16
#define S 8192
#define C 256      // K_CH = D_MODEL
#define OUT 256
#define SB 64            // rows per scores block
#define NSB (S / SB)     // 128 score partials per batch
#define VB 128           // rows per value block
#define NVB (S / VB)     // 64 value partials per batch

// ---------------- scratch (no allocations allowed) ----------------
__device__ float g_qk[B * C];          // Wk @ q  per batch/channel
__device__ float g_bdot[B];            // q . bk
__device__ float g_scores[B * S];      // raw scaled scores
__device__ float g_pm[B * NSB];        // per-block max
__device__ float g_pl[B * NSB];        // per-block sumexp
__device__ float g_cv[B * NVB * C];    // per-block normalized weighted value sums
__device__ float g_po[B * 8 * OUT];    // partial projected outputs (8 c-slices)

// ---------------- kernel 1: prep (grid (B,8), 256 thr) ---------------
// every block redundantly computes q (Wq stays L2-hot), then its 32
// channels of qk = Wk @ q; block y==0 also does bdot = q.bk
__global__ void prep_kernel(const float* __restrict__ query,
                            const float* __restrict__ Wq,
                            const float* __restrict__ bq,
                            const float* __restrict__ Wk,
                            const float* __restrict__ bk) {
    const int b = blockIdx.x;
    const int t = threadIdx.x;            // 0..255
    const int lane = t & 31, warp = t >> 5;
    __shared__ float q_sh[OUT];
    __shared__ float red[8];

    // redundant q projection (coalesced over t)
    float acc = bq[t];
    const float* qrow = query + b * C;
    #pragma unroll 8
    for (int d = 0; d < C; d++)
        acc += qrow[d] * Wq[d * OUT + t];
    q_sh[t] = acc;

    if (blockIdx.y == 0) {
        float v = acc * bk[t];
        #pragma unroll
        for (int off = 16; off; off >>= 1)
            v += __shfl_xor_sync(0xffffffffu, v, off);
        if (lane == 0) red[warp] = v;
    }
    __syncthreads();
    if (blockIdx.y == 0 && t == 0) {
        float s = red[0];
        #pragma unroll
        for (int i = 1; i < 8; i++) s += red[i];
        g_bdot[b] = s;
    }

    // qk: this block's 32 channels; warp handles 4 channels sequentially
    const float4* q4 = (const float4*)q_sh;
    #pragma unroll
    for (int i = 0; i < 4; i++) {
        const int c = blockIdx.y * 32 + warp * 4 + i;
        const float4* w4 = (const float4*)(Wk + (size_t)c * OUT);
        float a = 0.f;
        #pragma unroll
        for (int j = 0; j < 2; j++) {
            float4 w = w4[lane + 32 * j];
            float4 q = q4[lane + 32 * j];
            a += w.x * q.x + w.y * q.y + w.z * q.z + w.w * q.w;
        }
        #pragma unroll
        for (int off = 16; off; off >>= 1)
            a += __shfl_xor_sync(0xffffffffu, a, off);
        if (lane == 0) g_qk[b * C + c] = a;
    }
}

// ---------------- kernel 2: scores pass (grid (NSB,B), 256 thr) ------
// reads key once; each warp computes 8 rows, 4 in flight
__global__ void scores_kernel(const float* __restrict__ key) {
    const int b = blockIdx.y;
    const int s0 = blockIdx.x * SB;
    const int t = threadIdx.x, lane = t & 31, warp = t >> 5;

    __shared__ float qk_sh[C];
    __shared__ float sc_sh[SB];
    __shared__ float redm[2], redl[2];

    qk_sh[t] = g_qk[b * C + t];
    __syncthreads();

    const float bd = g_bdot[b];
    const float scale = 0.0625f;  // 1/sqrt(256)
    const float4* qk4 = (const float4*)qk_sh;

    #pragma unroll
    for (int half = 0; half < 2; half++) {
        const int r0 = warp * 8 + half * 4;
        const float* base = key + ((size_t)b * S + s0 + r0) * C;
        const float4* k0 = (const float4*)(base);
        const float4* k1 = (const float4*)(base + C);
        const float4* k2 = (const float4*)(base + 2 * C);
        const float4* k3 = (const float4*)(base + 3 * C);
        float a0 = 0.f, a1 = 0.f, a2 = 0.f, a3 = 0.f;
        #pragma unroll
        for (int j = 0; j < 2; j++) {
            const int idx = lane + 32 * j;
            float4 q = qk4[idx];
            float4 x0 = k0[idx];
            float4 x1 = k1[idx];
            float4 x2 = k2[idx];
            float4 x3 = k3[idx];
            a0 += x0.x * q.x + x0.y * q.y + x0.z * q.z + x0.w * q.w;
            a1 += x1.x * q.x + x1.y * q.y + x1.z * q.z + x1.w * q.w;
            a2 += x2.x * q.x + x2.y * q.y + x2.z * q.z + x2.w * q.w;
            a3 += x3.x * q.x + x3.y * q.y + x3.z * q.z + x3.w * q.w;
        }
        #pragma unroll
        for (int off = 16; off; off >>= 1) {
            a0 += __shfl_xor_sync(0xffffffffu, a0, off);
            a1 += __shfl_xor_sync(0xffffffffu, a1, off);
            a2 += __shfl_xor_sync(0xffffffffu, a2, off);
            a3 += __shfl_xor_sync(0xffffffffu, a3, off);
        }
        if (lane == 0) {
            sc_sh[r0]     = (a0 + bd) * scale;
            sc_sh[r0 + 1] = (a1 + bd) * scale;
            sc_sh[r0 + 2] = (a2 + bd) * scale;
            sc_sh[r0 + 3] = (a3 + bd) * scale;
        }
    }
    __syncthreads();

    // write raw scores + block-local softmax partials (threads 0..63)
    float sc = 0.f;
    if (t < SB) {
        sc = sc_sh[t];
        g_scores[(size_t)b * S + s0 + t] = sc;
        float v = sc;
        #pragma unroll
        for (int off = 16; off; off >>= 1)
            v = fmaxf(v, __shfl_xor_sync(0xffffffffu, v, off));
        if (lane == 0) redm[warp] = v;
    }
    __syncthreads();
    const float bm = fmaxf(redm[0], redm[1]);
    if (t < SB) {
        float p = __expf(sc - bm);
        #pragma unroll
        for (int off = 16; off; off >>= 1)
            p += __shfl_xor_sync(0xffffffffu, p, off);
        if (lane == 0) redl[warp] = p;
    }
    __syncthreads();
    if (t == 0) {
        g_pm[b * NSB + blockIdx.x] = bm;
        g_pl[b * NSB + blockIdx.x] = redl[0] + redl[1];
    }
}

// ---------------- kernel 3: value pass w/ fused global softmax -------
// grid (NVB, B), 256 thr; redundant L2-hot reduce of 128 partials,
// then float4 column walk: 4 row-groups x 64 channel-quads
__global__ void vaccum_kernel(const float* __restrict__ value) {
    const int b = blockIdx.y;
    const int s0 = blockIdx.x * VB;
    const int t = threadIdx.x, lane = t & 31, warp = t >> 5;

    __shared__ float w_sh[VB];
    __shared__ float redm[4], redl[4];
    __shared__ float4 red4[4][OUT / 4];

    // --- redundant global softmax reduce over NSB=128 partials (L2 hot)
    float pm = -INFINITY, pl = 0.f;
    if (t < NSB) {
        pm = g_pm[b * NSB + t];
        pl = g_pl[b * NSB + t];
    }
    float v = pm;
    #pragma unroll
    for (int off = 16; off; off >>= 1)
        v = fmaxf(v, __shfl_xor_sync(0xffffffffu, v, off));
    if (lane == 0) redm[warp] = v;
    __syncthreads();
    const float gm = fmaxf(fmaxf(redm[0], redm[1]), fmaxf(redm[2], redm[3]));
    float w = pl * __expf(pm - gm);
    #pragma unroll
    for (int off = 16; off; off >>= 1)
        w += __shfl_xor_sync(0xffffffffu, w, off);
    if (lane == 0) redl[warp] = w;
    __syncthreads();
    const float gli = 1.f / (redl[0] + redl[1] + redl[2] + redl[3]);

    // --- per-row weights for this chunk
    if (t < VB)
        w_sh[t] = __expf(g_scores[(size_t)b * S + s0 + t] - gm) * gli;
    __syncthreads();

    // --- float4 column walk: rg = row-group, cq = channel quad
    const int cq = t & 63;
    const int rg = t >> 6;
    const float4* vb = (const float4*)(value + ((size_t)b * S + s0) * C) + cq;
    float4 acc = make_float4(0.f, 0.f, 0.f, 0.f);
    #pragma unroll 4
    for (int s = rg; s < VB; s += 4) {
        const float4 x = vb[(size_t)s * (C / 4)];
        const float ws = w_sh[s];
        acc.x += ws * x.x; acc.y += ws * x.y;
        acc.z += ws * x.z; acc.w += ws * x.w;
    }
    red4[rg][cq] = acc;
    __syncthreads();

    if (t < 64) {
        float4 a0 = red4[0][t], a1 = red4[1][t], a2 = red4[2][t], a3 = red4[3][t];
        float4 r;
        r.x = (a0.x + a1.x) + (a2.x + a3.x);
        r.y = (a0.y + a1.y) + (a2.y + a3.y);
        r.z = (a0.z + a1.z) + (a2.z + a3.z);
        r.w = (a0.w + a1.w) + (a2.w + a3.w);
        ((float4*)(g_cv + ((size_t)(b * NVB + blockIdx.x)) * C))[t] = r;
    }
}

// ---------------- kernel 4: partial projection (grid (B,8), 256) -----
// block y owns channel slice c in [32y, 32y+32):
//   phase A: cx[32] = sum over 64 chunk partials (split across 8 warps)
//   phase B: po[t]  = sum_j cx[j] * Wv[(32y+j)*OUT + t]   (coalesced)
__global__ void project_part_kernel(const float* __restrict__ Wv) {
    const int b = blockIdx.x;
    const int y = blockIdx.y;
    const int t = threadIdx.x, lane = t & 31, warp = t >> 5;

    __shared__ float shA[8][32];
    __shared__ float cx_sh[32];

    // phase A: warp w sums partials i = 8w..8w+7 for channel (32y + lane)
    const size_t cvbase = ((size_t)(b * NVB + warp * 8)) * C + y * 32 + lane;
    float a = 0.f;
    #pragma unroll
    for (int i = 0; i < 8; i++)
        a += g_cv[cvbase + (size_t)i * C];
    shA[warp][lane] = a;
    __syncthreads();

    if (t < 32) {
        float s = shA[0][t];
        #pragma unroll
        for (int w = 1; w < 8; w++) s += shA[w][t];
        cx_sh[t] = s;
    }
    __syncthreads();

    // phase B: 32-iteration coalesced Wv walk
    float o = 0.f;
    const float* wv = Wv + (size_t)(y * 32) * OUT + t;
    #pragma unroll 8
    for (int j = 0; j < 32; j++)
        o += cx_sh[j] * wv[(size_t)j * OUT];
    g_po[(size_t)(b * 8 + y) * OUT + t] = o;
}

// ---------------- kernel 5: assemble ctx + broadcast over S ----------
// grid (S/64, B), 256 thr; ctx = bv + sum of 8 projection partials
__global__ void bcast_kernel(const float* __restrict__ bv,
                             float* __restrict__ out) {
    const int b = blockIdx.y;
    const int t = threadIdx.x;
    __shared__ float4 ctx4[OUT / 4];  // 64
    if (t < OUT / 4) {
        float4 acc = ((const float4*)bv)[t];
        const float4* po4 = (const float4*)(g_po + (size_t)b * 8 * OUT);
        #pragma unroll
        for (int y = 0; y < 8; y++) {
            const float4 p = po4[y * (OUT / 4) + t];
            acc.x += p.x; acc.y += p.y; acc.z += p.z; acc.w += p.w;
        }
        ctx4[t] = acc;
    }
    __syncthreads();

    const int row = t >> 6;   // 0..3
    const int col = t & 63;   // 0..63
    const float4 val = ctx4[col];
    float4* o4 = (float4*)out;
    const size_t base = ((size_t)b * S + (size_t)blockIdx.x * 64) * (C / 4);
    #pragma unroll
    for (int i = 0; i < 16; i++)
        __stcs(&o4[base + (size_t)(i * 4 + row) * (OUT / 4) + col], val);
}

// ---------------- launch ------------------
extern "C" void kernel_launch(void* const* d_in, const int* in_sizes, int n_in,
                              void* d_out, int out_size) {
    const float* query = (const float*)d_in[0];
    const float* key   = (const float*)d_in[1];
    const float* value = (const float*)d_in[2];
    const float* Wq    = (const float*)d_in[3];
    const float* bq    = (const float*)d_in[4];
    const float* Wk    = (const float*)d_in[5];
    const float* bk    = (const float*)d_in[6];
    const float* Wv    = (const float*)d_in[7];
    const float* bv    = (const float*)d_in[8];
    float* out = (float*)d_out;

    prep_kernel<<<dim3(B, 8), 256>>>(query, Wq, bq, Wk, bk);
    scores_kernel<<<dim3(NSB, B), 256>>>(key);
    vaccum_kernel<<<dim3(NVB, B), 256>>>(value);
    project_part_kernel<<<dim3(B, 8), 256>>>(Wv);
    bcast_kernel<<<dim3(S / 64, B), 256>>>(bv, out);
}

// round 9
// speedup vs baseline: 1.2387x; 1.0990x over previous
#include <cuda_runtime.h>
#include <math.h>

#define B 16
#define S 8192
#define C 256      // K_CH = D_MODEL
#define OUT 256
#define SB 128           // rows per scores block
#define NSB (S / SB)     // 64 score partials per batch
#define VB 128           // rows per value block
#define NVB (S / VB)     // 64 value partials per batch

// ---------------- scratch (no allocations allowed) ----------------
__device__ float g_qk[B * C];          // Wk @ q  per batch/channel
__device__ float g_bdot[B];            // q . bk
__device__ float g_scores[B * S];      // raw scaled scores
__device__ float g_pm[B * NSB];        // per-block max
__device__ float g_pl[B * NSB];        // per-block sumexp
__device__ float g_cv[B * NVB * C];    // per-block normalized weighted value sums
__device__ float g_po[B * 8 * OUT];    // partial projected outputs (8 c-slices)

// ---------------- kernel 1: prep (grid (B,8), 256 thr) ---------------
__global__ void prep_kernel(const float* __restrict__ query,
                            const float* __restrict__ Wq,
                            const float* __restrict__ bq,
                            const float* __restrict__ Wk,
                            const float* __restrict__ bk) {
    const int b = blockIdx.x;
    const int t = threadIdx.x;            // 0..255
    const int lane = t & 31, warp = t >> 5;
    __shared__ float q_sh[OUT];
    __shared__ float red[8];

    // redundant q projection (coalesced over t; Wq stays L2-hot)
    float acc = bq[t];
    const float* qrow = query + b * C;
    #pragma unroll 8
    for (int d = 0; d < C; d++)
        acc += qrow[d] * Wq[d * OUT + t];
    q_sh[t] = acc;

    if (blockIdx.y == 0) {
        float v = acc * bk[t];
        #pragma unroll
        for (int off = 16; off; off >>= 1)
            v += __shfl_xor_sync(0xffffffffu, v, off);
        if (lane == 0) red[warp] = v;
    }
    __syncthreads();
    if (blockIdx.y == 0 && t == 0) {
        float s = red[0];
        #pragma unroll
        for (int i = 1; i < 8; i++) s += red[i];
        g_bdot[b] = s;
    }

    // qk: this block's 32 channels; warp handles 4 channels sequentially
    const float4* q4 = (const float4*)q_sh;
    #pragma unroll
    for (int i = 0; i < 4; i++) {
        const int c = blockIdx.y * 32 + warp * 4 + i;
        const float4* w4 = (const float4*)(Wk + (size_t)c * OUT);
        float a = 0.f;
        #pragma unroll
        for (int j = 0; j < 2; j++) {
            float4 w = w4[lane + 32 * j];
            float4 q = q4[lane + 32 * j];
            a += w.x * q.x + w.y * q.y + w.z * q.z + w.w * q.w;
        }
        #pragma unroll
        for (int off = 16; off; off >>= 1)
            a += __shfl_xor_sync(0xffffffffu, a, off);
        if (lane == 0) g_qk[b * C + c] = a;
    }
}

// ---------------- kernel 2: scores pass (grid (NSB,B), 256 thr) ------
// reads key once (evict-first); each warp computes 16 rows, 4 in flight
__global__ void scores_kernel(const float* __restrict__ key) {
    const int b = blockIdx.y;
    const int s0 = blockIdx.x * SB;
    const int t = threadIdx.x, lane = t & 31, warp = t >> 5;

    __shared__ float qk_sh[C];
    __shared__ float sc_sh[SB];
    __shared__ float redm[4], redl[4];

    qk_sh[t] = g_qk[b * C + t];
    __syncthreads();

    const float bd = g_bdot[b];
    const float scale = 0.0625f;  // 1/sqrt(256)
    const float4* qk4 = (const float4*)qk_sh;

    #pragma unroll
    for (int g = 0; g < 4; g++) {
        const int r0 = warp * 16 + g * 4;
        const float* base = key + ((size_t)b * S + s0 + r0) * C;
        const float4* k0 = (const float4*)(base);
        const float4* k1 = (const float4*)(base + C);
        const float4* k2 = (const float4*)(base + 2 * C);
        const float4* k3 = (const float4*)(base + 3 * C);
        float a0 = 0.f, a1 = 0.f, a2 = 0.f, a3 = 0.f;
        #pragma unroll
        for (int j = 0; j < 2; j++) {
            const int idx = lane + 32 * j;
            float4 q = qk4[idx];
            float4 x0 = __ldcs(&k0[idx]);
            float4 x1 = __ldcs(&k1[idx]);
            float4 x2 = __ldcs(&k2[idx]);
            float4 x3 = __ldcs(&k3[idx]);
            a0 += x0.x * q.x + x0.y * q.y + x0.z * q.z + x0.w * q.w;
            a1 += x1.x * q.x + x1.y * q.y + x1.z * q.z + x1.w * q.w;
            a2 += x2.x * q.x + x2.y * q.y + x2.z * q.z + x2.w * q.w;
            a3 += x3.x * q.x + x3.y * q.y + x3.z * q.z + x3.w * q.w;
        }
        #pragma unroll
        for (int off = 16; off; off >>= 1) {
            a0 += __shfl_xor_sync(0xffffffffu, a0, off);
            a1 += __shfl_xor_sync(0xffffffffu, a1, off);
            a2 += __shfl_xor_sync(0xffffffffu, a2, off);
            a3 += __shfl_xor_sync(0xffffffffu, a3, off);
        }
        if (lane == 0) {
            sc_sh[r0]     = (a0 + bd) * scale;
            sc_sh[r0 + 1] = (a1 + bd) * scale;
            sc_sh[r0 + 2] = (a2 + bd) * scale;
            sc_sh[r0 + 3] = (a3 + bd) * scale;
        }
    }
    __syncthreads();

    // write raw scores + block-local softmax partials (threads 0..127)
    float sc = 0.f;
    if (t < SB) {
        sc = sc_sh[t];
        g_scores[(size_t)b * S + s0 + t] = sc;
        float v = sc;
        #pragma unroll
        for (int off = 16; off; off >>= 1)
            v = fmaxf(v, __shfl_xor_sync(0xffffffffu, v, off));
        if (lane == 0) redm[warp] = v;
    }
    __syncthreads();
    const float bm = fmaxf(fmaxf(redm[0], redm[1]), fmaxf(redm[2], redm[3]));
    if (t < SB) {
        float p = __expf(sc - bm);
        #pragma unroll
        for (int off = 16; off; off >>= 1)
            p += __shfl_xor_sync(0xffffffffu, p, off);
        if (lane == 0) redl[warp] = p;
    }
    __syncthreads();
    if (t == 0) {
        g_pm[b * NSB + blockIdx.x] = bm;
        g_pl[b * NSB + blockIdx.x] = redl[0] + redl[1] + redl[2] + redl[3];
    }
}

// ---------------- kernel 3: value pass w/ fused global softmax -------
// grid (NVB, B), 256 thr; redundant L2-hot reduce of 64 partials,
// then float4 column walk (unroll 8): 4 row-groups x 64 channel-quads
__global__ void vaccum_kernel(const float* __restrict__ value) {
    const int b = blockIdx.y;
    const int s0 = blockIdx.x * VB;
    const int t = threadIdx.x, lane = t & 31, warp = t >> 5;

    __shared__ float w_sh[VB];
    __shared__ float redm[2], redl[2];
    __shared__ float4 red4[4][OUT / 4];

    // --- redundant global softmax reduce over NSB=64 partials (L2 hot)
    float pm = -INFINITY, pl = 0.f;
    if (t < NSB) {
        pm = g_pm[b * NSB + t];
        pl = g_pl[b * NSB + t];
    }
    float v = pm;
    #pragma unroll
    for (int off = 16; off; off >>= 1)
        v = fmaxf(v, __shfl_xor_sync(0xffffffffu, v, off));
    if (lane == 0 && warp < 2) redm[warp] = v;
    __syncthreads();
    const float gm = fmaxf(redm[0], redm[1]);
    float w = pl * __expf(pm - gm);
    #pragma unroll
    for (int off = 16; off; off >>= 1)
        w += __shfl_xor_sync(0xffffffffu, w, off);
    if (lane == 0 && warp < 2) redl[warp] = w;
    __syncthreads();
    const float gli = 1.f / (redl[0] + redl[1]);

    // --- per-row weights for this chunk
    if (t < VB)
        w_sh[t] = __expf(g_scores[(size_t)b * S + s0 + t] - gm) * gli;
    __syncthreads();

    // --- float4 column walk: rg = row-group, cq = channel quad
    const int cq = t & 63;
    const int rg = t >> 6;
    const float4* vb = (const float4*)(value + ((size_t)b * S + s0) * C) + cq;
    float4 acc = make_float4(0.f, 0.f, 0.f, 0.f);
    #pragma unroll 8
    for (int s = rg; s < VB; s += 4) {
        const float4 x = __ldcs(&vb[(size_t)s * (C / 4)]);
        const float ws = w_sh[s];
        acc.x += ws * x.x; acc.y += ws * x.y;
        acc.z += ws * x.z; acc.w += ws * x.w;
    }
    red4[rg][cq] = acc;
    __syncthreads();

    if (t < 64) {
        float4 a0 = red4[0][t], a1 = red4[1][t], a2 = red4[2][t], a3 = red4[3][t];
        float4 r;
        r.x = (a0.x + a1.x) + (a2.x + a3.x);
        r.y = (a0.y + a1.y) + (a2.y + a3.y);
        r.z = (a0.z + a1.z) + (a2.z + a3.z);
        r.w = (a0.w + a1.w) + (a2.w + a3.w);
        ((float4*)(g_cv + ((size_t)(b * NVB + blockIdx.x)) * C))[t] = r;
    }
}

// ---------------- kernel 4: partial projection (grid (B,8), 256) -----
__global__ void project_part_kernel(const float* __restrict__ Wv) {
    const int b = blockIdx.x;
    const int y = blockIdx.y;
    const int t = threadIdx.x, lane = t & 31, warp = t >> 5;

    __shared__ float shA[8][32];
    __shared__ float cx_sh[32];

    // phase A: warp w sums partials i = 8w..8w+7 for channel (32y + lane)
    const size_t cvbase = ((size_t)(b * NVB + warp * 8)) * C + y * 32 + lane;
    float a = 0.f;
    #pragma unroll
    for (int i = 0; i < 8; i++)
        a += g_cv[cvbase + (size_t)i * C];
    shA[warp][lane] = a;
    __syncthreads();

    if (t < 32) {
        float s = shA[0][t];
        #pragma unroll
        for (int w = 1; w < 8; w++) s += shA[w][t];
        cx_sh[t] = s;
    }
    __syncthreads();

    // phase B: 32-iteration coalesced Wv walk
    float o = 0.f;
    const float* wv = Wv + (size_t)(y * 32) * OUT + t;
    #pragma unroll 8
    for (int j = 0; j < 32; j++)
        o += cx_sh[j] * wv[(size_t)j * OUT];
    g_po[(size_t)(b * 8 + y) * OUT + t] = o;
}

// ---------------- kernel 5: assemble ctx + broadcast over S ----------
__global__ void bcast_kernel(const float* __restrict__ bv,
                             float* __restrict__ out) {
    const int b = blockIdx.y;
    const int t = threadIdx.x;
    __shared__ float4 ctx4[OUT / 4];  // 64
    if (t < OUT / 4) {
        float4 acc = ((const float4*)bv)[t];
        const float4* po4 = (const float4*)(g_po + (size_t)b * 8 * OUT);
        #pragma unroll
        for (int y = 0; y < 8; y++) {
            const float4 p = po4[y * (OUT / 4) + t];
            acc.x += p.x; acc.y += p.y; acc.z += p.z; acc.w += p.w;
        }
        ctx4[t] = acc;
    }
    __syncthreads();

    const int row = t >> 6;   // 0..3
    const int col = t & 63;   // 0..63
    const float4 val = ctx4[col];
    float4* o4 = (float4*)out;
    const size_t base = ((size_t)b * S + (size_t)blockIdx.x * 64) * (C / 4);
    #pragma unroll
    for (int i = 0; i < 16; i++)
        __stcs(&o4[base + (size_t)(i * 4 + row) * (OUT / 4) + col], val);
}

// ---------------- launch ------------------
extern "C" void kernel_launch(void* const* d_in, const int* in_sizes, int n_in,
                              void* d_out, int out_size) {
    const float* query = (const float*)d_in[0];
    const float* key   = (const float*)d_in[1];
    const float* value = (const float*)d_in[2];
    const float* Wq    = (const float*)d_in[3];
    const float* bq    = (const float*)d_in[4];
    const float* Wk    = (const float*)d_in[5];
    const float* bk    = (const float*)d_in[6];
    const float* Wv    = (const float*)d_in[7];
    const float* bv    = (const float*)d_in[8];
    float* out = (float*)d_out;

    prep_kernel<<<dim3(B, 8), 256>>>(query, Wq, bq, Wk, bk);
    scores_kernel<<<dim3(NSB, B), 256>>>(key);
    vaccum_kernel<<<dim3(NVB, B), 256>>>(value);
    project_part_kernel<<<dim3(B, 8), 256>>>(Wv);
    bcast_kernel<<<dim3(S / 64, B), 256>>>(bv, out);
}

// round 10
// speedup vs baseline: 1.4004x; 1.1306x over previous
#include <cuda_runtime.h>
#include <math.h>

#define B 16
#define S 8192
#define C 256      // K_CH = D_MODEL
#define OUT 256
#define CHUNK 128
#define NCHUNK (S / CHUNK)   // 64

// ---------------- scratch (no allocations allowed) ----------------
__device__ float g_qk[B * C];            // Wk @ q  per batch/channel
__device__ float g_bdot[B];              // q . bk
__device__ float g_m[B * NCHUNK];        // per-chunk score max
__device__ float g_l[B * NCHUNK];        // per-chunk sumexp (local max)
__device__ float g_cv[B * NCHUNK * C];   // per-chunk UNNORMALIZED weighted value sums
__device__ float g_po[B * 8 * OUT];      // partial projected outputs (8 c-slices)

// ---------------- kernel 1: prep (grid (B,8), 256 thr) ---------------
__global__ void prep_kernel(const float* __restrict__ query,
                            const float* __restrict__ Wq,
                            const float* __restrict__ bq,
                            const float* __restrict__ Wk,
                            const float* __restrict__ bk) {
    const int b = blockIdx.x;
    const int t = threadIdx.x;            // 0..255
    const int lane = t & 31, warp = t >> 5;
    __shared__ float q_sh[OUT];
    __shared__ float red[8];

    // redundant q projection (coalesced over t; Wq stays L2-hot)
    float acc = bq[t];
    const float* qrow = query + b * C;
    #pragma unroll 8
    for (int d = 0; d < C; d++)
        acc += qrow[d] * Wq[d * OUT + t];
    q_sh[t] = acc;

    if (blockIdx.y == 0) {
        float v = acc * bk[t];
        #pragma unroll
        for (int off = 16; off; off >>= 1)
            v += __shfl_xor_sync(0xffffffffu, v, off);
        if (lane == 0) red[warp] = v;
    }
    __syncthreads();
    if (blockIdx.y == 0 && t == 0) {
        float s = red[0];
        #pragma unroll
        for (int i = 1; i < 8; i++) s += red[i];
        g_bdot[b] = s;
    }

    // qk: this block's 32 channels; warp handles 4 channels sequentially
    const float4* q4 = (const float4*)q_sh;
    #pragma unroll
    for (int i = 0; i < 4; i++) {
        const int c = blockIdx.y * 32 + warp * 4 + i;
        const float4* w4 = (const float4*)(Wk + (size_t)c * OUT);
        float a = 0.f;
        #pragma unroll
        for (int j = 0; j < 2; j++) {
            float4 w = w4[lane + 32 * j];
            float4 q = q4[lane + 32 * j];
            a += w.x * q.x + w.y * q.y + w.z * q.z + w.w * q.w;
        }
        #pragma unroll
        for (int off = 16; off; off >>= 1)
            a += __shfl_xor_sync(0xffffffffu, a, off);
        if (lane == 0) g_qk[b * C + c] = a;
    }
}

// ---------------- kernel 2: fused key+value scan (grid (NCHUNK,B)) ---
// phase 1: scores for CHUNK rows (reads key, 4 rows in flight / warp)
// phase 2: local softmax + unnormalized weighted value sums (reads value)
__global__ void partial_kernel(const float* __restrict__ key,
                               const float* __restrict__ value) {
    const int b = blockIdx.y;
    const int s0 = blockIdx.x * CHUNK;
    const int t = threadIdx.x, lane = t & 31, warp = t >> 5;

    __shared__ float qk_sh[C];
    __shared__ float p_sh[CHUNK];
    __shared__ float redm[4], redl[4];
    __shared__ float4 red4[4][OUT / 4];

    qk_sh[t] = g_qk[b * C + t];
    __syncthreads();

    const float bd = g_bdot[b];
    const float scale = 0.0625f;  // 1/sqrt(256)
    const float4* qk4 = (const float4*)qk_sh;

    // ---- phase 1: each warp 16 rows, 4 in flight
    #pragma unroll
    for (int g = 0; g < 4; g++) {
        const int r0 = warp * 16 + g * 4;
        const float* base = key + ((size_t)b * S + s0 + r0) * C;
        const float4* k0 = (const float4*)(base);
        const float4* k1 = (const float4*)(base + C);
        const float4* k2 = (const float4*)(base + 2 * C);
        const float4* k3 = (const float4*)(base + 3 * C);
        float a0 = 0.f, a1 = 0.f, a2 = 0.f, a3 = 0.f;
        #pragma unroll
        for (int j = 0; j < 2; j++) {
            const int idx = lane + 32 * j;
            float4 q = qk4[idx];
            float4 x0 = __ldcs(&k0[idx]);
            float4 x1 = __ldcs(&k1[idx]);
            float4 x2 = __ldcs(&k2[idx]);
            float4 x3 = __ldcs(&k3[idx]);
            a0 += x0.x * q.x + x0.y * q.y + x0.z * q.z + x0.w * q.w;
            a1 += x1.x * q.x + x1.y * q.y + x1.z * q.z + x1.w * q.w;
            a2 += x2.x * q.x + x2.y * q.y + x2.z * q.z + x2.w * q.w;
            a3 += x3.x * q.x + x3.y * q.y + x3.z * q.z + x3.w * q.w;
        }
        #pragma unroll
        for (int off = 16; off; off >>= 1) {
            a0 += __shfl_xor_sync(0xffffffffu, a0, off);
            a1 += __shfl_xor_sync(0xffffffffu, a1, off);
            a2 += __shfl_xor_sync(0xffffffffu, a2, off);
            a3 += __shfl_xor_sync(0xffffffffu, a3, off);
        }
        if (lane == 0) {
            p_sh[r0]     = (a0 + bd) * scale;
            p_sh[r0 + 1] = (a1 + bd) * scale;
            p_sh[r0 + 2] = (a2 + bd) * scale;
            p_sh[r0 + 3] = (a3 + bd) * scale;
        }
    }
    __syncthreads();

    // ---- local softmax partials over this chunk (threads 0..127)
    float sc = 0.f;
    if (t < CHUNK) {
        sc = p_sh[t];
        float v = sc;
        #pragma unroll
        for (int off = 16; off; off >>= 1)
            v = fmaxf(v, __shfl_xor_sync(0xffffffffu, v, off));
        if (lane == 0) redm[warp] = v;
    }
    __syncthreads();
    const float m = fmaxf(fmaxf(redm[0], redm[1]), fmaxf(redm[2], redm[3]));
    float p = 0.f;
    if (t < CHUNK) {
        p = __expf(sc - m);
        float sv = p;
        #pragma unroll
        for (int off = 16; off; off >>= 1)
            sv += __shfl_xor_sync(0xffffffffu, sv, off);
        if (lane == 0) redl[warp] = sv;
    }
    __syncthreads();
    if (t < CHUNK) p_sh[t] = p;   // unnormalized weights
    __syncthreads();

    // ---- phase 2: float4 column walk, unroll 8
    const int cq = t & 63;
    const int rg = t >> 6;
    const float4* vb = (const float4*)(value + ((size_t)b * S + s0) * C) + cq;
    float4 acc = make_float4(0.f, 0.f, 0.f, 0.f);
    #pragma unroll 8
    for (int s = rg; s < CHUNK; s += 4) {
        const float4 x = __ldcs(&vb[(size_t)s * (C / 4)]);
        const float ws = p_sh[s];
        acc.x += ws * x.x; acc.y += ws * x.y;
        acc.z += ws * x.z; acc.w += ws * x.w;
    }
    red4[rg][cq] = acc;
    __syncthreads();

    const int pidx = b * NCHUNK + blockIdx.x;
    if (t < 64) {
        float4 a0 = red4[0][t], a1 = red4[1][t], a2 = red4[2][t], a3 = red4[3][t];
        float4 r;
        r.x = (a0.x + a1.x) + (a2.x + a3.x);
        r.y = (a0.y + a1.y) + (a2.y + a3.y);
        r.z = (a0.z + a1.z) + (a2.z + a3.z);
        r.w = (a0.w + a1.w) + (a2.w + a3.w);
        ((float4*)(g_cv + (size_t)pidx * C))[t] = r;
    }
    if (t == 0) {
        g_m[pidx] = m;
        g_l[pidx] = redl[0] + redl[1] + redl[2] + redl[3];
    }
}

// ---------------- kernel 3: softmax fixup + projection (grid (B,8)) --
// block y owns channel slice [32y, 32y+32):
//   gm/gl: redundant reduce over 64 L2-hot (m,l) pairs
//   phase A: cx[32] = sum_i exp(m_i - gm) * cv_i  (8 warps x 8 chunks)
//   phase B: po[t]  = (1/gl) * sum_j cx[j] * Wv[(32y+j)*OUT + t]
__global__ void project_part_kernel(const float* __restrict__ Wv) {
    const int b = blockIdx.x;
    const int y = blockIdx.y;
    const int t = threadIdx.x, lane = t & 31, warp = t >> 5;

    __shared__ float redm[2], redl[2];
    __shared__ float shA[8][32];
    __shared__ float cx_sh[32];

    // --- gm / gl (threads 0..63 hold the 64 chunk partials)
    float pm = -INFINITY, pl = 0.f;
    if (t < NCHUNK) {
        pm = g_m[b * NCHUNK + t];
        pl = g_l[b * NCHUNK + t];
    }
    float v = pm;
    #pragma unroll
    for (int off = 16; off; off >>= 1)
        v = fmaxf(v, __shfl_xor_sync(0xffffffffu, v, off));
    if (lane == 0 && warp < 2) redm[warp] = v;
    __syncthreads();
    const float gm = fmaxf(redm[0], redm[1]);
    float w = pl * __expf(pm - gm);
    #pragma unroll
    for (int off = 16; off; off >>= 1)
        w += __shfl_xor_sync(0xffffffffu, w, off);
    if (lane == 0 && warp < 2) redl[warp] = w;
    __syncthreads();
    const float gli = 1.f / (redl[0] + redl[1]);

    // --- phase A: warp w sums chunks i = 8w..8w+7 with weight exp(m_i-gm)
    const size_t cvbase = ((size_t)(b * NCHUNK + warp * 8)) * C + y * 32 + lane;
    float a = 0.f;
    #pragma unroll
    for (int i = 0; i < 8; i++) {
        const float wi = __expf(g_m[b * NCHUNK + warp * 8 + i] - gm);
        a += wi * g_cv[cvbase + (size_t)i * C];
    }
    shA[warp][lane] = a;
    __syncthreads();

    if (t < 32) {
        float s = shA[0][t];
        #pragma unroll
        for (int ww = 1; ww < 8; ww++) s += shA[ww][t];
        cx_sh[t] = s * gli;
    }
    __syncthreads();

    // --- phase B: 32-iteration coalesced Wv walk
    float o = 0.f;
    const float* wv = Wv + (size_t)(y * 32) * OUT + t;
    #pragma unroll 8
    for (int j = 0; j < 32; j++)
        o += cx_sh[j] * wv[(size_t)j * OUT];
    g_po[(size_t)(b * 8 + y) * OUT + t] = o;
}

// ---------------- kernel 4: assemble ctx + broadcast over S ----------
__global__ void bcast_kernel(const float* __restrict__ bv,
                             float* __restrict__ out) {
    const int b = blockIdx.y;
    const int t = threadIdx.x;
    __shared__ float4 ctx4[OUT / 4];  // 64
    if (t < OUT / 4) {
        float4 acc = ((const float4*)bv)[t];
        const float4* po4 = (const float4*)(g_po + (size_t)b * 8 * OUT);
        #pragma unroll
        for (int y = 0; y < 8; y++) {
            const float4 p = po4[y * (OUT / 4) + t];
            acc.x += p.x; acc.y += p.y; acc.z += p.z; acc.w += p.w;
        }
        ctx4[t] = acc;
    }
    __syncthreads();

    const int row = t >> 6;   // 0..3
    const int col = t & 63;   // 0..63
    const float4 val = ctx4[col];
    float4* o4 = (float4*)out;
    const size_t base = ((size_t)b * S + (size_t)blockIdx.x * 64) * (C / 4);
    #pragma unroll
    for (int i = 0; i < 16; i++)
        __stcs(&o4[base + (size_t)(i * 4 + row) * (OUT / 4) + col], val);
}

// ---------------- launch ------------------
extern "C" void kernel_launch(void* const* d_in, const int* in_sizes, int n_in,
                              void* d_out, int out_size) {
    const float* query = (const float*)d_in[0];
    const float* key   = (const float*)d_in[1];
    const float* value = (const float*)d_in[2];
    const float* Wq    = (const float*)d_in[3];
    const float* bq    = (const float*)d_in[4];
    const float* Wk    = (const float*)d_in[5];
    const float* bk    = (const float*)d_in[6];
    const float* Wv    = (const float*)d_in[7];
    const float* bv    = (const float*)d_in[8];
    float* out = (float*)d_out;

    prep_kernel<<<dim3(B, 8), 256>>>(query, Wq, bq, Wk, bk);
    partial_kernel<<<dim3(NCHUNK, B), 256>>>(key, value);
    project_part_kernel<<<dim3(B, 8), 256>>>(Wv);
    bcast_kernel<<<dim3(S / 64, B), 256>>>(bv, out);
}